// round 7
// baseline (speedup 1.0000x reference)
#include <cuda_runtime.h>
#include <cuda_bf16.h>

#define N_NODES 100000
#define N_EDGES 1600000
#define IN_DIM  256
#define HIDDEN  64

#define DEG_BLOCKS 3125      // 800000 threads, 2 edges each = 1.6M edges exactly
#define DOT_BLOCKS 12500     // 8 warps/block, warp per node = 100000 nodes

// Scratch (__device__ globals; zero at module load, k_out re-zeros for replay)
__device__ __align__(16) float g_u[IN_DIM];   // W @ w2
__device__ float g_c;                          // b.w2 + b2
__device__ int   g_ready;                      // u-published flag
__device__ float g_deg[N_NODES];               // edge count (self loop = +1 later)
__device__ float g_ss[N_NODES];                // raw s[v], then *= dinv in k_norm
__device__ float g_dinv[N_NODES];
__device__ float g_t[N_NODES];                 // edge-aggregated ss[src]

// K1 fused: deg blocks do edge-degree atomics (block 0 also publishes u,c);
//           dot blocks stream x and compute raw s[v] = x[v].u
__global__ void __launch_bounds__(256) k_main(
        const float* __restrict__ x, const int* __restrict__ dst,
        const float* __restrict__ W, const float* __restrict__ b,
        const float* __restrict__ w2, const float* __restrict__ b2) {
    if (blockIdx.x < DEG_BLOCKS) {
        // ---- degree side ----
        int t2 = blockIdx.x * 256 + threadIdx.x;
        int2 p = *(const int2*)(dst + (size_t)t2 * 2);
        if ((unsigned)p.x < (unsigned)N_NODES) atomicAdd(&g_deg[p.x], 1.0f);
        if ((unsigned)p.y < (unsigned)N_NODES) atomicAdd(&g_deg[p.y], 1.0f);
        if (blockIdx.x == 0) {
            int i = threadIdx.x;  // 256 == IN_DIM
            float acc = 0.f;
#pragma unroll
            for (int h = 0; h < HIDDEN; h++) acc += W[i * HIDDEN + h] * w2[h];
            g_u[i] = acc;
            if (i == 0) {
                float cc = b2[0];
                for (int h = 0; h < HIDDEN; h++) cc += b[h] * w2[h];
                g_c = cc;
            }
            __threadfence();
            __syncthreads();
            if (i == 0) atomicExch(&g_ready, 1);
        }
    } else {
        // ---- dot side: warp per node ----
        int node = (blockIdx.x - DEG_BLOCKS) * 8 + (threadIdx.x >> 5);
        int lane = threadIdx.x & 31;
        if (threadIdx.x == 0) {
            while (atomicAdd(&g_ready, 0) == 0) { __nanosleep(64); }
        }
        __syncthreads();
        __threadfence();   // acquire g_u
        if (node >= N_NODES) return;
        const float4* xp = (const float4*)(x + (size_t)node * IN_DIM);
        const float4* up = (const float4*)g_u;
        float4 a0 = xp[lane];
        float4 a1 = xp[lane + 32];
        float4 u0 = up[lane];
        float4 u1 = up[lane + 32];
        float acc = a0.x * u0.x + a0.y * u0.y + a0.z * u0.z + a0.w * u0.w
                  + a1.x * u1.x + a1.y * u1.y + a1.z * u1.z + a1.w * u1.w;
#pragma unroll
        for (int o = 16; o; o >>= 1) acc += __shfl_xor_sync(0xffffffffu, acc, o);
        if (lane == 0) g_ss[node] = acc;   // raw; dinv applied in k_norm
    }
}

// K2: ss *= rsqrt(1+deg); dinv stored
__global__ void __launch_bounds__(128) k_norm() {
    int v = blockIdx.x * 128 + threadIdx.x;
    if (v < N_NODES) {
        float di = rsqrtf(1.0f + g_deg[v]);
        g_dinv[v] = di;
        g_ss[v] *= di;
    }
}

// K3: scatter ss[src] into t[dst]; 2 edges/thread, int2 index loads
__global__ void __launch_bounds__(256) k_scatter(const int* __restrict__ src,
                                                 const int* __restrict__ dst) {
    int t2 = blockIdx.x * 256 + threadIdx.x;
    size_t e = (size_t)t2 * 2;
    int2 s = *(const int2*)(src + e);
    int2 d = *(const int2*)(dst + e);
    float v0 = ((unsigned)s.x < (unsigned)N_NODES) ? g_ss[s.x] : 0.f;
    float v1 = ((unsigned)s.y < (unsigned)N_NODES) ? g_ss[s.y] : 0.f;
    if ((unsigned)d.x < (unsigned)N_NODES) atomicAdd(&g_t[d.x], v0);
    if ((unsigned)d.y < (unsigned)N_NODES) atomicAdd(&g_t[d.y], v1);
}

// K4: out = sigmoid(dinv*(t + ss) + c); reset state for next replay
__global__ void __launch_bounds__(128) k_out(float* __restrict__ out) {
    int v = blockIdx.x * 128 + threadIdx.x;
    if (v < N_NODES) {
        float z = g_dinv[v] * (g_t[v] + g_ss[v]) + g_c;
        out[v] = 1.0f / (1.0f + expf(-z));
        g_deg[v] = 0.0f;
        g_t[v] = 0.0f;
        if (v == 0) g_ready = 0;
    }
}

extern "C" void kernel_launch(void* const* d_in, const int* in_sizes, int n_in,
                              void* d_out, int out_size) {
    const float* x   = (const float*)d_in[0];
    const int*   ei  = (const int*)d_in[1];   // [2, N_EDGES], materialized as int32
    const float* W   = (const float*)d_in[2];
    const float* b   = (const float*)d_in[3];
    const float* w2  = (const float*)d_in[4];
    const float* b2  = (const float*)d_in[5];
    float*       out = (float*)d_out;

    const int* src = ei;
    const int* dst = ei + N_EDGES;

    k_main<<<DEG_BLOCKS + DOT_BLOCKS, 256>>>(x, dst, W, b, w2, b2);
    k_norm<<<(N_NODES + 127) / 128, 128>>>();
    k_scatter<<<DEG_BLOCKS, 256>>>(src, dst);
    k_out<<<(N_NODES + 127) / 128, 128>>>(out);
}

// round 8
// speedup vs baseline: 1.0817x; 1.0817x over previous
#include <cuda_runtime.h>
#include <cuda_bf16.h>
#include <cooperative_groups.h>
namespace cg = cooperative_groups;

#define N_NODES 100000
#define N_EDGES 1600000
#define IN_DIM  256
#define HIDDEN  64

// Scratch (__device__ globals; zero at module load; phases restore zeros for replay)
__device__ __align__(16) float g_u[IN_DIM];   // W @ w2
__device__ float g_c;                          // b.w2 + b2
__device__ float g_deg[N_NODES];               // edge count (self loop = +1 in dinv)
__device__ float g_ss[N_NODES];                // s[v]*dinv[v]
__device__ float g_dinv[N_NODES];
__device__ float g_t[N_NODES];                 // edge-aggregated ss[src]

__global__ void __launch_bounds__(256) k_all(
        const float* __restrict__ x,
        const int* __restrict__ src, const int* __restrict__ dst,
        const float* __restrict__ W, const float* __restrict__ b,
        const float* __restrict__ w2, const float* __restrict__ b2,
        float* __restrict__ out) {
    cg::grid_group grid = cg::this_grid();
    const int gtid = blockIdx.x * blockDim.x + threadIdx.x;
    const int gsz  = gridDim.x * blockDim.x;

    // ---- Phase 0: u,c (block 0) + degree atomics (all blocks) ----
    if (blockIdx.x == 0) {
        int i = threadIdx.x;  // 256 == IN_DIM
        float acc = 0.f;
#pragma unroll
        for (int h = 0; h < HIDDEN; h++) acc += W[i * HIDDEN + h] * w2[h];
        g_u[i] = acc;
        if (i == 0) {
            float cc = b2[0];
            for (int h = 0; h < HIDDEN; h++) cc += b[h] * w2[h];
            g_c = cc;
        }
    }
    for (int i = gtid; i < N_EDGES / 2; i += gsz) {
        int2 p = ((const int2*)dst)[i];
        if ((unsigned)p.x < (unsigned)N_NODES) atomicAdd(&g_deg[p.x], 1.0f);
        if ((unsigned)p.y < (unsigned)N_NODES) atomicAdd(&g_deg[p.y], 1.0f);
    }
    grid.sync();

    // ---- Phase 1: dot, warp per node, 2 nodes per iteration (MLP=4) ----
    {
        const int warp  = gtid >> 5;
        const int lane  = gtid & 31;
        const int nwarp = gsz >> 5;
        const float4* up = (const float4*)g_u;
        const float4 u0 = up[lane];
        const float4 u1 = up[lane + 32];
        for (int n0 = warp; n0 < N_NODES; n0 += 2 * nwarp) {
            int n1 = n0 + nwarp;
            const float4* xp0 = (const float4*)(x + (size_t)n0 * IN_DIM);
            float4 a0 = xp0[lane];
            float4 a1 = xp0[lane + 32];
            float4 b0, b1;
            if (n1 < N_NODES) {
                const float4* xp1 = (const float4*)(x + (size_t)n1 * IN_DIM);
                b0 = xp1[lane];
                b1 = xp1[lane + 32];
            }
            float acc0 = a0.x*u0.x + a0.y*u0.y + a0.z*u0.z + a0.w*u0.w
                       + a1.x*u1.x + a1.y*u1.y + a1.z*u1.z + a1.w*u1.w;
            float acc1 = 0.f;
            if (n1 < N_NODES)
                acc1 = b0.x*u0.x + b0.y*u0.y + b0.z*u0.z + b0.w*u0.w
                     + b1.x*u1.x + b1.y*u1.y + b1.z*u1.z + b1.w*u1.w;
#pragma unroll
            for (int o = 16; o; o >>= 1) {
                acc0 += __shfl_xor_sync(0xffffffffu, acc0, o);
                acc1 += __shfl_xor_sync(0xffffffffu, acc1, o);
            }
            if (lane == 0) {
                float di0 = rsqrtf(1.0f + g_deg[n0]);
                g_dinv[n0] = di0;
                g_ss[n0] = acc0 * di0;
                if (n1 < N_NODES) {
                    float di1 = rsqrtf(1.0f + g_deg[n1]);
                    g_dinv[n1] = di1;
                    g_ss[n1] = acc1 * di1;
                }
            }
        }
    }
    grid.sync();

    // ---- Phase 2: edge scatter + reset g_deg ----
    for (int i = gtid; i < N_EDGES / 2; i += gsz) {
        int2 s = ((const int2*)src)[i];
        int2 d = ((const int2*)dst)[i];
        float v0 = ((unsigned)s.x < (unsigned)N_NODES) ? g_ss[s.x] : 0.f;
        float v1 = ((unsigned)s.y < (unsigned)N_NODES) ? g_ss[s.y] : 0.f;
        if ((unsigned)d.x < (unsigned)N_NODES) atomicAdd(&g_t[d.x], v0);
        if ((unsigned)d.y < (unsigned)N_NODES) atomicAdd(&g_t[d.y], v1);
    }
    for (int v = gtid; v < N_NODES; v += gsz) g_deg[v] = 0.0f;
    grid.sync();

    // ---- Phase 3: output + reset g_t ----
    for (int v = gtid; v < N_NODES; v += gsz) {
        float z = g_dinv[v] * (g_t[v] + g_ss[v]) + g_c;
        out[v] = 1.0f / (1.0f + expf(-z));
        g_t[v] = 0.0f;
    }
}

extern "C" void kernel_launch(void* const* d_in, const int* in_sizes, int n_in,
                              void* d_out, int out_size) {
    const float* x   = (const float*)d_in[0];
    const int*   ei  = (const int*)d_in[1];   // [2, N_EDGES], materialized as int32
    const float* W   = (const float*)d_in[2];
    const float* b   = (const float*)d_in[3];
    const float* w2  = (const float*)d_in[4];
    const float* b2  = (const float*)d_in[5];
    float*       out = (float*)d_out;

    const int* src = ei;
    const int* dst = ei + N_EDGES;

    int dev = 0, sms = 0, bpm = 0;
    cudaGetDevice(&dev);
    cudaDeviceGetAttribute(&sms, cudaDevAttrMultiProcessorCount, dev);
    cudaOccupancyMaxActiveBlocksPerMultiprocessor(&bpm, (const void*)k_all, 256, 0);
    if (bpm < 1) bpm = 1;
    int blocks = sms * bpm;

    void* args[] = {(void*)&x, (void*)&src, (void*)&dst, (void*)&W, (void*)&b,
                    (void*)&w2, (void*)&b2, (void*)&out};
    cudaLaunchCooperativeKernel((const void*)k_all, dim3(blocks), dim3(256),
                                args, 0, (cudaStream_t)0);
}